// round 6
// baseline (speedup 1.0000x reference)
#include <cuda_runtime.h>
#include <cstdint>

typedef unsigned long long ull;

// Packed f32x2 FMA / ADD — only reachable via PTX (ptxas never auto-fuses).
#define FMA2(d, a, b, c) \
    asm("fma.rn.f32x2 %0, %1, %2, %3;" : "=l"(d) : "l"(a), "l"(b), "l"(c))
#define ADD2(d, a, b) \
    asm("add.rn.f32x2 %0, %1, %2;" : "=l"(d) : "l"(a), "l"(b))

__device__ __forceinline__ ull pack2(float lo, float hi) {
    ull r;
    asm("mov.b64 %0, {%1, %2};" : "=l"(r) : "f"(lo), "f"(hi));
    return r;
}
__device__ __forceinline__ void stg_cs(float* p, ull v) {
    asm volatile("st.global.cs.b64 [%0], %1;" :: "l"(p), "l"(v) : "memory");
}

namespace {
constexpr int H  = 224;
constexpr int W  = 224;
constexpr int HO = 222;
constexpr int WO = 222;
constexpr int OC = 64;
constexpr int TPB = 256;     // 8 warps = 8 channels
constexpr int SPITCH = 68;   // smem row pitch (floats)
constexpr int SROWS  = 113;  // input rows per phase
}

// Warp = (b, ch, x-chunk): lanes cover 64 output cols (2 each), loop over rows.
// Weights live in registers for the whole thread; input window slides by row.
// Block = 8 channels sharing one staged input strip.
__global__ __launch_bounds__(TPB, 4)
void Conv2d_68298569941797_kernel(const float* __restrict__ data,
                                  const float* __restrict__ weight,
                                  float* __restrict__ out) {
    __shared__ float s_in[SROWS * SPITCH];   // 113 x 68 floats = 30.7 KB

    const int tid   = threadIdx.x;
    const int wid   = tid >> 5;
    const int lane  = tid & 31;
    const int c     = blockIdx.x;            // x chunk 0..3
    const int b     = blockIdx.z;
    const int ch    = blockIdx.y * 8 + wid;
    const int xbase = 64 * c;
    const int cols  = (xbase + SPITCH <= W) ? SPITCH : (W - xbase);  // 68 or 32
    const int nvec  = cols >> 2;             // float4s per staged row

    // Weights for this warp's channel: 9 taps, duplicated into both f32x2 lanes.
    ull wreg[9];
#pragma unroll
    for (int k = 0; k < 9; ++k) {
        float wv = __ldg(weight + ch * 9 + k);
        wreg[k] = pack2(wv, wv);
    }

    const int x      = xbase + 2 * lane;     // lane's output col pair
    const bool active = (x + 1 < WO);        // chunk 3: lanes 15..31 idle
    const int lc     = 2 * lane;             // local col in strip

    const size_t plane = (size_t)HO * WO;
    const float* dsrc  = data + ((size_t)b * H) * W + xbase;

#pragma unroll
    for (int phase = 0; phase < 2; ++phase) {
        const int gr0 = phase ? 111 : 0;     // first staged input row

        // ── Stage input rows gr0 .. gr0+112 (cols xbase .. xbase+cols-1) ──
        if (phase) __syncthreads();          // all compute on old buffer done
        for (int i = tid; i < SROWS * nvec; i += TPB) {
            int rr = i / nvec;
            int v  = i - rr * nvec;
            *reinterpret_cast<float4*>(s_in + rr * SPITCH + 4 * v) =
                *reinterpret_cast<const float4*>(dsrc + (size_t)(gr0 + rr) * W + 4 * v);
        }
        __syncthreads();

        if (active) {
            // Prime the 3-row sliding pair window: rows 0 and 1 of the strip.
            ull P[3][3];
#pragma unroll
            for (int rr = 0; rr < 2; ++rr) {
                float2 u = *reinterpret_cast<const float2*>(s_in + rr * SPITCH + lc);
                float2 v = *reinterpret_cast<const float2*>(s_in + rr * SPITCH + lc + 2);
                P[rr][0] = pack2(u.x, u.y);
                P[rr][1] = pack2(u.y, v.x);
                P[rr][2] = pack2(v.x, v.y);
            }

            float* op = out + (((size_t)b * OC + ch) * HO + gr0) * WO + x;

#pragma unroll 3
            for (int ly = 0; ly < 111; ++ly) {
                // Load the new bottom row (strip row ly+2) into the rotating slot.
                const int rn = (ly + 2) % 3;
                {
                    const float* rp = s_in + (ly + 2) * SPITCH + lc;
                    float2 u = *reinterpret_cast<const float2*>(rp);
                    float2 v = *reinterpret_cast<const float2*>(rp + 2);
                    P[rn][0] = pack2(u.x, u.y);
                    P[rn][1] = pack2(u.y, v.x);
                    P[rn][2] = pack2(v.x, v.y);
                }
                const int r0 = ly % 3;         // input row y   (tap row 0)
                const int r1 = (ly + 1) % 3;   // input row y+1 (tap row 1)
                const int r2 = rn;             // input row y+2 (tap row 2)

                // Two independent chains, joined once.
                ull Aa = 0ull, Ab = 0ull;
                FMA2(Aa, P[r0][0], wreg[0], Aa);
                FMA2(Ab, P[r0][1], wreg[1], Ab);
                FMA2(Aa, P[r0][2], wreg[2], Aa);
                FMA2(Ab, P[r1][0], wreg[3], Ab);
                FMA2(Aa, P[r1][1], wreg[4], Aa);
                FMA2(Ab, P[r1][2], wreg[5], Ab);
                FMA2(Aa, P[r2][0], wreg[6], Aa);
                FMA2(Ab, P[r2][1], wreg[7], Ab);
                FMA2(Aa, P[r2][2], wreg[8], Aa);
                ull acc;
                ADD2(acc, Aa, Ab);

                stg_cs(op, acc);               // STG.64, coalesced, evict-first
                op += WO;
            }
        }
    }
}

extern "C" void kernel_launch(void* const* d_in, const int* in_sizes, int n_in,
                              void* d_out, int out_size) {
    const float* data   = (const float*)d_in[0];
    const float* weight = (const float*)d_in[1];
    float* out          = (float*)d_out;

    dim3 grid(4, OC / 8, 32);   // (x-chunks, channel groups, batches) = 1024 blocks
    Conv2d_68298569941797_kernel<<<grid, TPB>>>(data, weight, out);
}